// round 3
// baseline (speedup 1.0000x reference)
#include <cuda_runtime.h>

// NT-Xent loss, fused. N = 4096 rows (concat z_i,z_j), D = 256, C = 100.
// Pipeline: prep (normalize rows + labels + zero accumulators) ->
//           symmetric tiled sim GEMM with fused exp/mask epilogue ->
//           final ratio reduction.

#define BATCH 2048
#define N_TOT 4096
#define DDIM  256
#define CCLS  100

#define BM 128
#define BN 128
#define BK 8
#define NTILE (N_TOT / BM)          // 32
#define NTRI  (NTILE * (NTILE + 1) / 2)  // 528 upper-triangle tiles

// Scratch (no cudaMalloc allowed). g_zn is read via float4 -> force 16B align.
__device__ __align__(16) float g_zn[N_TOT * DDIM];   // normalized rows
__device__ int   g_lab[N_TOT];
__device__ float g_den[N_TOT];
__device__ float g_nom[N_TOT];

// ---------------------------------------------------------------------------
// exp(x) on [-1,1] via degree-9 Taylor (Horner, 9 FMA). |abs err| < 3e-7.
// Keeps the epilogue on the FMA pipe (MUFU.EX2 at rt=8/SMSP would cost ~63us
// for 8.4M exps — same order as the whole GEMM).
__device__ __forceinline__ float exp_poly(float x) {
    float p = 2.7557319e-6f;              // 1/9!
    p = fmaf(p, x, 2.4801587e-5f);        // 1/8!
    p = fmaf(p, x, 1.9841270e-4f);        // 1/7!
    p = fmaf(p, x, 1.3888889e-3f);        // 1/6!
    p = fmaf(p, x, 8.3333333e-3f);        // 1/5!
    p = fmaf(p, x, 4.1666667e-2f);        // 1/4!
    p = fmaf(p, x, 1.6666667e-1f);        // 1/3!
    p = fmaf(p, x, 0.5f);                 // 1/2!
    p = fmaf(p, x, 1.0f);
    p = fmaf(p, x, 1.0f);
    return p;
}

// ---------------------------------------------------------------------------
// Prep: one block per output row (4096 blocks x 256 threads).
// Normalizes the row, zeroes accumulators, extracts labels from one-hot.
__global__ void k_prep(const float* __restrict__ zi,
                       const float* __restrict__ zj,
                       const float* __restrict__ dist) {
    int row = blockIdx.x;
    int tid = threadIdx.x;
    const float* src = (row < BATCH) ? (zi + (size_t)row * DDIM)
                                     : (zj + (size_t)(row - BATCH) * DDIM);
    float v = src[tid];
    float ss = v * v;
    __shared__ float red[8];
    #pragma unroll
    for (int o = 16; o; o >>= 1) ss += __shfl_xor_sync(0xffffffffu, ss, o);
    if ((tid & 31) == 0) red[tid >> 5] = ss;
    __syncthreads();
    __shared__ float s_rn;
    __shared__ int   s_lab;
    if (tid == 0) {
        float t = 0.f;
        #pragma unroll
        for (int i = 0; i < 8; i++) t += red[i];
        s_rn = sqrtf(t);
        g_den[row] = 0.f;
        g_nom[row] = 0.f;
    }
    if (row < BATCH && tid < CCLS) {
        if (dist[(size_t)row * CCLS + tid] > 0.5f) s_lab = tid;  // exactly one hot
    }
    __syncthreads();
    g_zn[(size_t)row * DDIM + tid] = v / s_rn;
    if (row < BATCH && tid == 0) {
        g_lab[row] = s_lab;
        g_lab[row + BATCH] = s_lab;
    }
}

// ---------------------------------------------------------------------------
// Symmetric tiled similarity kernel. Only upper-triangle 128x128 tiles.
// Off-diagonal tiles scatter exp/mask sums to BOTH row and column sides.
__global__ void __launch_bounds__(256, 2) k_sim() {
    // decode linear tile id -> (br, bc) with bc >= br
    int t = blockIdx.x;
    int br = 0;
    while (t >= (NTILE - br)) { t -= (NTILE - br); br++; }
    int bc = br + t;
    bool diagTile = (br == bc);

    __shared__ float As[BK][BM];
    __shared__ float Bs[BK][BN];

    int tid = threadIdx.x;
    int tx = tid & 15;
    int ty = tid >> 4;

    // loader mapping: each thread loads one float4 of A and one of B per chunk
    int ldRow = tid >> 1;              // 0..127
    int ldK   = (tid & 1) * 4;         // 0 or 4

    const float* aBase = g_zn + (size_t)(br * BM + ldRow) * DDIM;
    const float* bBase = g_zn + (size_t)(bc * BN + ldRow) * DDIM;

    float acc[8][8];
    #pragma unroll
    for (int i = 0; i < 8; i++)
        #pragma unroll
        for (int j = 0; j < 8; j++) acc[i][j] = 0.f;

    for (int k0 = 0; k0 < DDIM; k0 += BK) {
        float4 av = *(const float4*)(aBase + k0 + ldK);
        float4 bv = *(const float4*)(bBase + k0 + ldK);
        __syncthreads();
        As[ldK + 0][ldRow] = av.x; As[ldK + 1][ldRow] = av.y;
        As[ldK + 2][ldRow] = av.z; As[ldK + 3][ldRow] = av.w;
        Bs[ldK + 0][ldRow] = bv.x; Bs[ldK + 1][ldRow] = bv.y;
        Bs[ldK + 2][ldRow] = bv.z; Bs[ldK + 3][ldRow] = bv.w;
        __syncthreads();
        #pragma unroll
        for (int kk = 0; kk < BK; kk++) {
            float a[8], b[8];
            *(float4*)&a[0] = *(const float4*)&As[kk][ty * 4];
            *(float4*)&a[4] = *(const float4*)&As[kk][ty * 4 + 64];
            *(float4*)&b[0] = *(const float4*)&Bs[kk][tx * 4];
            *(float4*)&b[4] = *(const float4*)&Bs[kk][tx * 4 + 64];
            #pragma unroll
            for (int i = 0; i < 8; i++)
                #pragma unroll
                for (int j = 0; j < 8; j++)
                    acc[i][j] = fmaf(a[i], b[j], acc[i][j]);
        }
    }

    // epilogue
    int rowIdx[8], colIdx[8], labR[8], labC[8];
    #pragma unroll
    for (int i = 0; i < 8; i++) {
        int ro = (i < 4) ? (ty * 4 + i) : (64 + ty * 4 + (i - 4));
        int co = (i < 4) ? (tx * 4 + i) : (64 + tx * 4 + (i - 4));
        rowIdx[i] = br * BM + ro;
        colIdx[i] = bc * BN + co;
        labR[i] = g_lab[rowIdx[i]];
        labC[i] = g_lab[colIdx[i]];
    }

    float denR[8], nomR[8], denC[8], nomC[8];
    #pragma unroll
    for (int i = 0; i < 8; i++) { denR[i]=0.f; nomR[i]=0.f; denC[i]=0.f; nomC[i]=0.f; }

    #pragma unroll
    for (int i = 0; i < 8; i++) {
        #pragma unroll
        for (int j = 0; j < 8; j++) {
            float s = acc[i][j];
            if (rowIdx[i] != colIdx[j]) {
                float e = exp_poly(s);
                float m = (labR[i] == labC[j]) ? s : 0.f;
                denR[i] += e;
                nomR[i] += m;
                denC[j] += e;
                nomC[j] += m;
            }
        }
    }

    #pragma unroll
    for (int i = 0; i < 8; i++) {
        atomicAdd(&g_den[rowIdx[i]], denR[i]);
        atomicAdd(&g_nom[rowIdx[i]], nomR[i]);
    }
    if (!diagTile) {
        #pragma unroll
        for (int j = 0; j < 8; j++) {
            atomicAdd(&g_den[colIdx[j]], denC[j]);
            atomicAdd(&g_nom[colIdx[j]], nomC[j]);
        }
    }
}

// ---------------------------------------------------------------------------
// Final: 128 threads, strided partials, warp-shuffle tree finish.
__global__ void k_final(float* __restrict__ out) {
    __shared__ float part[4];
    int tid = threadIdx.x;  // 128 threads
    float s = 0.f;
    #pragma unroll
    for (int i = 0; i < 32; i++) {
        int n = tid + i * 128;
        s += g_nom[n] / g_den[n];
    }
    #pragma unroll
    for (int o = 16; o; o >>= 1) s += __shfl_xor_sync(0xffffffffu, s, o);
    if ((tid & 31) == 0) part[tid >> 5] = s;
    __syncthreads();
    if (tid == 0) {
        out[0] = (part[0] + part[1] + part[2] + part[3]) / 4096.0f;
    }
}

// ---------------------------------------------------------------------------
extern "C" void kernel_launch(void* const* d_in, const int* in_sizes, int n_in,
                              void* d_out, int out_size) {
    const float* zi   = (const float*)d_in[0];
    const float* zj   = (const float*)d_in[1];
    // d_in[2] = z_n is dead code in the reference
    const float* dist = (const float*)d_in[3];
    float* out = (float*)d_out;

    k_prep<<<N_TOT, 256>>>(zi, zj, dist);
    k_sim<<<NTRI, 256>>>();
    k_final<<<1, 128>>>(out);
}

// round 5
// speedup vs baseline: 1.9108x; 1.9108x over previous
#include <cuda_runtime.h>
#include <cuda_bf16.h>
#include <cstdint>

// NT-Xent loss. N=4096 (concat z_i,z_j), D=256, C=100.
// sim GEMM on mma.sync.m16n8k16 bf16 (sm_100 base target; tcgen05 needs 'a').
// Exact-enough 3-way bf16 split: x = hi + lo;  sim = hi*hi' + hi*lo' + lo*hi'
// (dropped lo*lo' ~ 2e-7 abs). One shared [hi|lo] array (512 halves/row, 4MB);
// extended K=768 realized by per-chunk offset maps A=[hi,hi,lo], B=[hi,lo,hi].
// Symmetric upper-triangle 128x128 tiles; fused exp/mask epilogue scatters row
// sums + mirrored column sums via shuffle reductions and global atomics.

#define BATCH 2048
#define N_TOT 4096
#define DDIM  256
#define CCLS  100
#define TS    128
#define NTILE (N_TOT / TS)                 // 32
#define NTRI  (NTILE * (NTILE + 1) / 2)    // 528
#define NCH   48                           // K chunks of 16 halves
#define SROW  24                           // smem row stride in halves (48B, pad)
#define STAGEB (TS * SROW * 2)             // 6144 bytes per stage per operand

__device__ __align__(16) __nv_bfloat16 g_AB[(size_t)N_TOT * 512];  // [hi(256)|lo(256)]
__device__ int   g_lab[N_TOT];
__device__ float g_den[N_TOT];
__device__ float g_nom[N_TOT];

// ---------------------------------------------------------------------------
__device__ __forceinline__ uint32_t smem_u32(const void* p) {
    uint32_t a;
    asm("{ .reg .u64 t; cvta.to.shared.u64 t, %1; cvt.u32.u64 %0, t; }" : "=r"(a) : "l"(p));
    return a;
}
#define LDSM_X4(r0, r1, r2, r3, addr) \
    asm volatile("ldmatrix.sync.aligned.m8n8.x4.shared.b16 {%0,%1,%2,%3}, [%4];" \
                 : "=r"(r0), "=r"(r1), "=r"(r2), "=r"(r3) : "r"(addr))

__device__ __forceinline__ void mma16816(float* d, const uint32_t* a,
                                         uint32_t b0, uint32_t b1) {
    asm volatile("mma.sync.aligned.m16n8k16.row.col.f32.bf16.bf16.f32 "
                 "{%0,%1,%2,%3}, {%4,%5,%6,%7}, {%8,%9}, {%0,%1,%2,%3};"
                 : "+f"(d[0]), "+f"(d[1]), "+f"(d[2]), "+f"(d[3])
                 : "r"(a[0]), "r"(a[1]), "r"(a[2]), "r"(a[3]), "r"(b0), "r"(b1));
}

// exp(x) on [-1,1], degree-9 Taylor (Horner). |abs err| < 3e-7, fma pipe only.
__device__ __forceinline__ float exp_poly(float x) {
    float p = 2.7557319e-6f;
    p = fmaf(p, x, 2.4801587e-5f);
    p = fmaf(p, x, 1.9841270e-4f);
    p = fmaf(p, x, 1.3888889e-3f);
    p = fmaf(p, x, 8.3333333e-3f);
    p = fmaf(p, x, 4.1666667e-2f);
    p = fmaf(p, x, 1.6666667e-1f);
    p = fmaf(p, x, 0.5f);
    p = fmaf(p, x, 1.0f);
    p = fmaf(p, x, 1.0f);
    return p;
}

// chunk -> source offset (halves) in the 512-half row
__device__ __forceinline__ int offA(int c) {         // [hi, hi, lo]
    return (c < 32) ? ((c & 15) * 16) : (256 + (c - 32) * 16);
}
__device__ __forceinline__ int offB(int c) {         // [hi, lo, hi]
    return (c < 16) ? (c * 16) : ((c < 32) ? (256 + (c - 16) * 16) : ((c - 32) * 16));
}

// ---------------------------------------------------------------------------
// Prep: normalize, split hi/lo bf16, labels, zero accumulators.
__global__ void k_prep(const float* __restrict__ zi,
                       const float* __restrict__ zj,
                       const float* __restrict__ dist) {
    int row = blockIdx.x;
    int tid = threadIdx.x;
    const float* src = (row < BATCH) ? (zi + (size_t)row * DDIM)
                                     : (zj + (size_t)(row - BATCH) * DDIM);
    float v = src[tid];
    float ss = v * v;
    __shared__ float red[8];
    #pragma unroll
    for (int o = 16; o; o >>= 1) ss += __shfl_xor_sync(0xffffffffu, ss, o);
    if ((tid & 31) == 0) red[tid >> 5] = ss;
    __syncthreads();
    __shared__ float s_rn;
    __shared__ int   s_lab;
    if (tid == 0) {
        float t = 0.f;
        #pragma unroll
        for (int i = 0; i < 8; i++) t += red[i];
        s_rn = sqrtf(t);
        g_den[row] = 0.f;
        g_nom[row] = 0.f;
    }
    if (row < BATCH && tid < CCLS) {
        if (dist[(size_t)row * CCLS + tid] > 0.5f) s_lab = tid;  // exactly one hot
    }
    __syncthreads();
    float x = v / s_rn;
    __nv_bfloat16 hi = __float2bfloat16(x);
    __nv_bfloat16 lo = __float2bfloat16(x - __bfloat162float(hi));
    size_t b = (size_t)row * 512;
    g_AB[b + tid]       = hi;
    g_AB[b + 256 + tid] = lo;
    if (row < BATCH && tid == 0) {
        g_lab[row] = s_lab;
        g_lab[row + BATCH] = s_lab;
    }
}

// ---------------------------------------------------------------------------
// k_sim: one 128x128 upper-triangle tile per CTA. 256 threads, 8 warps (4x2).
__global__ void __launch_bounds__(256, 2) k_sim() {
    __shared__ __align__(16) __nv_bfloat16 As[2][TS * SROW];
    __shared__ __align__(16) __nv_bfloat16 Bs[2][TS * SROW];
    __shared__ int sLabR[TS], sLabC[TS];

    int tid  = threadIdx.x;
    int lane = tid & 31;
    int wid  = tid >> 5;
    int wm   = wid & 3;        // 4 warps over M
    int wn   = wid >> 2;       // 2 warps over N

    // decode linear tile id -> (br, bc), bc >= br
    int t = blockIdx.x;
    int br = 0;
    while (t >= (NTILE - br)) { t -= (NTILE - br); br++; }
    int bc = br + t;
    bool diag = (br == bc);

    if (tid < TS) {
        sLabR[tid] = g_lab[br * TS + tid];
        sLabC[tid] = g_lab[bc * TS + tid];
    }

    // global loaders: each thread owns (row = tid>>1, 16B half = tid&1) per chunk
    int lrow = tid >> 1, lhalf = tid & 1;
    const uint4* gA = (const uint4*)g_AB + (size_t)(br * TS + lrow) * 64;
    const uint4* gB = (const uint4*)g_AB + (size_t)(bc * TS + lrow) * 64;
    char* stsA = (char*)As + (size_t)lrow * 48 + lhalf * 16;
    char* stsB = (char*)Bs + (size_t)lrow * 48 + lhalf * 16;

    // ldmatrix base addresses (stage 0)
    uint32_t aAddr = smem_u32(As) + ((wm * 32 + (lane & 15)) * SROW + (lane >> 4) * 8) * 2;
    uint32_t bAddr = smem_u32(Bs) + ((wn * 64 + (lane & 15)) * SROW + (lane >> 4) * 8) * 2;

    float acc[2][8][4];
    #pragma unroll
    for (int i = 0; i < 2; i++)
        #pragma unroll
        for (int j = 0; j < 8; j++)
            #pragma unroll
            for (int k = 0; k < 4; k++) acc[i][j][k] = 0.f;

    uint4 pa = gA[offA(0) / 8 + lhalf];
    uint4 pb = gB[offB(0) / 8 + lhalf];
    *(uint4*)stsA = pa;
    *(uint4*)stsB = pb;
    __syncthreads();

    #pragma unroll 1
    for (int c = 0; c < NCH; c++) {
        int st = c & 1;
        if (c + 1 < NCH) {
            pa = gA[offA(c + 1) / 8 + lhalf];
            pb = gB[offB(c + 1) / 8 + lhalf];
        }
        uint32_t a0[4], a1[4];
        LDSM_X4(a0[0], a0[1], a0[2], a0[3], aAddr + st * STAGEB);
        LDSM_X4(a1[0], a1[1], a1[2], a1[3], aAddr + st * STAGEB + 16 * 48);
        #pragma unroll
        for (int ntp = 0; ntp < 4; ntp++) {
            uint32_t b[4];
            LDSM_X4(b[0], b[1], b[2], b[3], bAddr + st * STAGEB + ntp * 16 * 48);
            mma16816(acc[0][ntp * 2],     a0, b[0], b[2]);
            mma16816(acc[0][ntp * 2 + 1], a0, b[1], b[3]);
            mma16816(acc[1][ntp * 2],     a1, b[0], b[2]);
            mma16816(acc[1][ntp * 2 + 1], a1, b[1], b[3]);
        }
        if (c + 1 < NCH) {
            *(uint4*)(stsA + (st ^ 1) * STAGEB) = pa;
            *(uint4*)(stsB + (st ^ 1) * STAGEB) = pb;
        }
        __syncthreads();
    }

    // ---------------- epilogue ----------------
    // acc[mt][n8][q]: rows wm*32+mt*16+(lane>>2)+{0,8}; cols wn*64+n8*8+(lane&3)*2+{0,1}
    int r0 = wm * 32 + (lane >> 2);
    int c0 = wn * 64 + (lane & 3) * 2;

    float rowDen[2][2] = {{0.f, 0.f}, {0.f, 0.f}};
    float rowNom[2][2] = {{0.f, 0.f}, {0.f, 0.f}};
    float colDen[8][2], colNom[8][2];
    #pragma unroll
    for (int n8 = 0; n8 < 8; n8++) {
        colDen[n8][0] = colDen[n8][1] = 0.f;
        colNom[n8][0] = colNom[n8][1] = 0.f;
    }

    #pragma unroll
    for (int mt = 0; mt < 2; mt++) {
        #pragma unroll
        for (int h = 0; h < 2; h++) {
            int rloc = r0 + mt * 16 + h * 8;
            int grow = br * TS + rloc;
            int lr = sLabR[rloc];
            #pragma unroll
            for (int n8 = 0; n8 < 8; n8++) {
                #pragma unroll
                for (int j = 0; j < 2; j++) {
                    int cloc = c0 + n8 * 8 + j;
                    float s = acc[mt][n8][h * 2 + j];
                    bool valid = (grow != bc * TS + cloc);
                    float e = valid ? exp_poly(s) : 0.f;
                    float m = (valid && lr == sLabC[cloc]) ? s : 0.f;
                    rowDen[mt][h] += e;  rowNom[mt][h] += m;
                    colDen[n8][j] += e;  colNom[n8][j] += m;
                }
            }
        }
    }

    // row sums: reduce across lane&3 (cols); lanes with lane%4==0 hold result
    #pragma unroll
    for (int mt = 0; mt < 2; mt++)
        #pragma unroll
        for (int h = 0; h < 2; h++) {
            #pragma unroll
            for (int o = 1; o <= 2; o <<= 1) {
                rowDen[mt][h] += __shfl_xor_sync(0xffffffffu, rowDen[mt][h], o);
                rowNom[mt][h] += __shfl_xor_sync(0xffffffffu, rowNom[mt][h], o);
            }
            if ((lane & 3) == 0) {
                int grow = br * TS + r0 + mt * 16 + h * 8;
                atomicAdd(&g_den[grow], rowDen[mt][h]);
                atomicAdd(&g_nom[grow], rowNom[mt][h]);
            }
        }

    // col sums (mirror side): reduce across lane>>2 (rows); lanes 0-3 hold result
    if (!diag) {
        #pragma unroll
        for (int n8 = 0; n8 < 8; n8++)
            #pragma unroll
            for (int j = 0; j < 2; j++) {
                #pragma unroll
                for (int o = 4; o <= 16; o <<= 1) {
                    colDen[n8][j] += __shfl_xor_sync(0xffffffffu, colDen[n8][j], o);
                    colNom[n8][j] += __shfl_xor_sync(0xffffffffu, colNom[n8][j], o);
                }
                if (lane < 4) {
                    int gcol = bc * TS + wn * 64 + n8 * 8 + (lane & 3) * 2 + j;
                    atomicAdd(&g_den[gcol], colDen[n8][j]);
                    atomicAdd(&g_nom[gcol], colNom[n8][j]);
                }
            }
    }
}

// ---------------------------------------------------------------------------
__global__ void k_final(float* __restrict__ out) {
    __shared__ float part[4];
    int tid = threadIdx.x;  // 128
    float s = 0.f;
    #pragma unroll
    for (int i = 0; i < 32; i++) {
        int n = tid + i * 128;
        s += g_nom[n] / g_den[n];
    }
    #pragma unroll
    for (int o = 16; o; o >>= 1) s += __shfl_xor_sync(0xffffffffu, s, o);
    if ((tid & 31) == 0) part[tid >> 5] = s;
    __syncthreads();
    if (tid == 0) out[0] = (part[0] + part[1] + part[2] + part[3]) / 4096.0f;
}

// ---------------------------------------------------------------------------
extern "C" void kernel_launch(void* const* d_in, const int* in_sizes, int n_in,
                              void* d_out, int out_size) {
    const float* zi   = (const float*)d_in[0];
    const float* zj   = (const float*)d_in[1];
    // d_in[2] = z_n is dead code in the reference
    const float* dist = (const float*)d_in[3];
    float* out = (float*)d_out;

    k_prep<<<N_TOT, 256>>>(zi, zj, dist);
    k_sim<<<NTRI, 256>>>();
    k_final<<<1, 128>>>(out);
}

// round 6
// speedup vs baseline: 1.9542x; 1.0227x over previous
#include <cuda_runtime.h>
#include <cuda_bf16.h>
#include <cstdint>

// NT-Xent loss. N=4096 (concat z_i,z_j), D=256, C=100.
// sim GEMM on mma.sync.m16n8k16 bf16. Exact-enough 3-way bf16 split:
//   x = hi + lo;  sim = hi*hi' + hi*lo' + lo*hi'  (dropped lo*lo' ~ 2e-7 abs)
// One shared [hi(256)|lo(256)] array; extended K=768 via per-chunk offset maps
// A=[hi,hi,lo], B=[hi,lo,hi].
// Tiles: 256x128, only tiles with some element gr<gc (C >= 2R), 272 tiles.
// Epilogue rule: accumulate element (gr,gc) iff gr<gc, scatter to BOTH row gr
// and col gc -> every unordered pair counted exactly once, no diag special case.
// Mainloop: 3-stage cp.async pipeline, K-chunks of 32, one bar per chunk.

#define BATCH 2048
#define N_TOT 4096
#define TM    256
#define TN    128
#define NTILER (N_TOT / TM)               // 16
#define NTILES 272                        // sum_{R=0..15} (32-2R)
#define NCH   24                          // K chunks of 32 halves (K_ext=768)
#define SROWB 80                          // smem row stride bytes (5*16B: conflict-free)
#define A_STG (TM * SROWB)                // 20480 B per A stage
#define B_STG (TN * SROWB)                // 10240 B per B stage
#define B_OFF (3 * A_STG)                 // 61440
#define SMEM_DYN (3 * A_STG + 3 * B_STG)  // 92160 B

__device__ __align__(16) __nv_bfloat16 g_AB[(size_t)N_TOT * 512];  // [hi|lo]
__device__ int   g_lab[N_TOT];
__device__ float g_den[N_TOT];
__device__ float g_nom[N_TOT];

// ---------------------------------------------------------------------------
__device__ __forceinline__ uint32_t smem_u32(const void* p) {
    uint32_t a;
    asm("{ .reg .u64 t; cvta.to.shared.u64 t, %1; cvt.u32.u64 %0, t; }" : "=r"(a) : "l"(p));
    return a;
}
#define LDSM_X4(r0, r1, r2, r3, addr) \
    asm volatile("ldmatrix.sync.aligned.m8n8.x4.shared.b16 {%0,%1,%2,%3}, [%4];" \
                 : "=r"(r0), "=r"(r1), "=r"(r2), "=r"(r3) : "r"(addr))
__device__ __forceinline__ void cp_async16(uint32_t dst, const void* src) {
    asm volatile("cp.async.cg.shared.global [%0], [%1], 16;" :: "r"(dst), "l"(src));
}
#define CP_COMMIT() asm volatile("cp.async.commit_group;" ::: "memory")
#define CP_WAIT1()  asm volatile("cp.async.wait_group 1;" ::: "memory")

__device__ __forceinline__ void mma16816(float* d, const uint32_t* a,
                                         uint32_t b0, uint32_t b1) {
    asm volatile("mma.sync.aligned.m16n8k16.row.col.f32.bf16.bf16.f32 "
                 "{%0,%1,%2,%3}, {%4,%5,%6,%7}, {%8,%9}, {%0,%1,%2,%3};"
                 : "+f"(d[0]), "+f"(d[1]), "+f"(d[2]), "+f"(d[3])
                 : "r"(a[0]), "r"(a[1]), "r"(a[2]), "r"(a[3]), "r"(b0), "r"(b1));
}

// exp(x) on [-1,1], degree-9 Taylor (Horner). |abs err| < 3e-7, fma pipe only.
__device__ __forceinline__ float exp_poly(float x) {
    float p = 2.7557319e-6f;
    p = fmaf(p, x, 2.4801587e-5f);
    p = fmaf(p, x, 1.9841270e-4f);
    p = fmaf(p, x, 1.3888889e-3f);
    p = fmaf(p, x, 8.3333333e-3f);
    p = fmaf(p, x, 4.1666667e-2f);
    p = fmaf(p, x, 1.6666667e-1f);
    p = fmaf(p, x, 0.5f);
    p = fmaf(p, x, 1.0f);
    p = fmaf(p, x, 1.0f);
    return p;
}

// ---------------------------------------------------------------------------
// Prep: 1024 blocks x 256 threads; 4 rows per block, float4 per thread (MLP 4).
__global__ void k_prep(const float* __restrict__ zi,
                       const float* __restrict__ zj,
                       const float* __restrict__ dist) {
    int tid  = threadIdx.x;
    int g    = tid >> 6;          // row group 0..3
    int t    = tid & 63;          // thread within row
    int lane = tid & 31, wid = tid >> 5;
    int row  = blockIdx.x * 4 + g;
    int srow = (row < BATCH) ? row : row - BATCH;
    const float* src = ((row < BATCH) ? zi : zj) + (size_t)srow * 256;

    float4 v = ((const float4*)src)[t];
    float ss = v.x * v.x + v.y * v.y + v.z * v.z + v.w * v.w;
    #pragma unroll
    for (int o = 16; o; o >>= 1) ss += __shfl_xor_sync(0xffffffffu, ss, o);

    __shared__ float wsum[8];
    __shared__ int   slab[4];
    if (lane == 0) wsum[wid] = ss;
    if (t < 50) {                 // scan 100 one-hot entries with 2 checks
        if (dist[(size_t)srow * 100 + t] > 0.5f)      slab[g] = t;
        if (dist[(size_t)srow * 100 + t + 50] > 0.5f) slab[g] = t + 50;
    }
    __syncthreads();

    float rn = 1.0f / sqrtf(wsum[2 * g] + wsum[2 * g + 1]);
    float x0 = v.x * rn, x1 = v.y * rn, x2 = v.z * rn, x3 = v.w * rn;
    __nv_bfloat16 h0 = __float2bfloat16(x0), h1 = __float2bfloat16(x1);
    __nv_bfloat16 h2 = __float2bfloat16(x2), h3 = __float2bfloat16(x3);
    __nv_bfloat16 l0 = __float2bfloat16(x0 - __bfloat162float(h0));
    __nv_bfloat16 l1 = __float2bfloat16(x1 - __bfloat162float(h1));
    __nv_bfloat16 l2 = __float2bfloat16(x2 - __bfloat162float(h2));
    __nv_bfloat16 l3 = __float2bfloat16(x3 - __bfloat162float(h3));

    __nv_bfloat162* hp = (__nv_bfloat162*)(g_AB + (size_t)row * 512);
    hp[t * 2]           = __nv_bfloat162(h0, h1);
    hp[t * 2 + 1]       = __nv_bfloat162(h2, h3);
    hp[128 + t * 2]     = __nv_bfloat162(l0, l1);
    hp[128 + t * 2 + 1] = __nv_bfloat162(l2, l3);

    if (t == 0) {
        g_den[row] = 0.f;
        g_nom[row] = 0.f;
        g_lab[row] = slab[g];
    }
}

// ---------------------------------------------------------------------------
// k_sim: one 256x128 tile per CTA. 8 warps (4 over M x 2 over N), 64x64/warp.
__global__ void __launch_bounds__(256, 1) k_sim() {
    extern __shared__ char sm[];
    __shared__ int sLabR[TM], sLabC[TN];

    int tid  = threadIdx.x;
    int lane = tid & 31;
    int wid  = tid >> 5;
    int wm   = wid & 3;           // 4 warps over M (64 rows each)
    int wn   = wid >> 2;          // 2 warps over N (64 cols each)

    // decode linear tile id -> (R, C) with C >= 2R
    int t = blockIdx.x;
    int R = 0;
    while (t >= (32 - 2 * R)) { t -= (32 - 2 * R); R++; }
    int C = 2 * R + t;
    int rowA0 = R * TM;
    int rowB0 = C * TN;

    if (tid < TM) sLabR[tid] = g_lab[rowA0 + tid];
    if (tid < TN) sLabC[tid] = g_lab[rowB0 + tid];

    uint32_t smB = smem_u32(sm);

    // cp.async issue of chunk c into stage st (A: 1024 x16B, B: 512 x16B)
    auto issue = [&](int c, int st) {
        int offA = (c < 8) ? c * 32 : ((c < 16) ? (c - 8) * 32 : 256 + (c - 16) * 32);
        int offB = (c < 8) ? c * 32 : ((c < 16) ? 256 + (c - 8) * 32 : (c - 16) * 32);
        #pragma unroll
        for (int u = 0; u < 4; u++) {
            int idx = tid + u * 256, r = idx >> 2, ks = idx & 3;
            cp_async16(smB + st * A_STG + r * SROWB + ks * 16,
                       g_AB + (size_t)(rowA0 + r) * 512 + offA + ks * 8);
        }
        #pragma unroll
        for (int u = 0; u < 2; u++) {
            int idx = tid + u * 256, r = idx >> 2, ks = idx & 3;
            cp_async16(smB + B_OFF + st * B_STG + r * SROWB + ks * 16,
                       g_AB + (size_t)(rowB0 + r) * 512 + offB + ks * 8);
        }
        CP_COMMIT();
    };

    float acc[4][8][4];
    #pragma unroll
    for (int i = 0; i < 4; i++)
        #pragma unroll
        for (int j = 0; j < 8; j++)
            #pragma unroll
            for (int k = 0; k < 4; k++) acc[i][j][k] = 0.f;

    issue(0, 0);
    issue(1, 1);

    uint32_t aLane = (uint32_t)((wm * 64 + (lane & 15)) * SROWB + (lane >> 4) * 16);
    uint32_t bLane = (uint32_t)(B_OFF + (wn * 64 + (lane & 15)) * SROWB + (lane >> 4) * 16);

    #pragma unroll 1
    for (int c = 0; c < NCH; c++) {
        int st = c % 3;
        CP_WAIT1();               // chunk c landed (chunk c+1 may be in flight)
        __syncthreads();          // all warps done with chunk c-1's stage
        if (c + 2 < NCH) issue(c + 2, (c + 2) % 3);
        else CP_COMMIT();         // keep group accounting uniform

        uint32_t aBase = smB + st * A_STG + aLane;
        uint32_t bBase = smB + st * B_STG + bLane;
        #pragma unroll
        for (int ks = 0; ks < 2; ks++) {
            uint32_t A[4][4];
            #pragma unroll
            for (int mt = 0; mt < 4; mt++)
                LDSM_X4(A[mt][0], A[mt][1], A[mt][2], A[mt][3],
                        aBase + mt * 16 * SROWB + ks * 32);
            #pragma unroll
            for (int ntp = 0; ntp < 4; ntp++) {
                uint32_t b[4];
                LDSM_X4(b[0], b[1], b[2], b[3], bBase + ntp * 16 * SROWB + ks * 32);
                #pragma unroll
                for (int mt = 0; mt < 4; mt++) {
                    mma16816(acc[mt][ntp * 2],     A[mt], b[0], b[2]);
                    mma16816(acc[mt][ntp * 2 + 1], A[mt], b[1], b[3]);
                }
            }
        }
    }

    // ---------------- epilogue: accumulate iff gr < gc, scatter both sides ---
    int mrow = lane >> 2;         // 0..7
    int ncol = (lane & 3) * 2;

    float cd[8][2], cm[8][2];
    #pragma unroll
    for (int n8 = 0; n8 < 8; n8++) { cd[n8][0] = cd[n8][1] = 0.f; cm[n8][0] = cm[n8][1] = 0.f; }

    #pragma unroll
    for (int mt = 0; mt < 4; mt++) {
        #pragma unroll
        for (int h = 0; h < 2; h++) {
            int rloc = wm * 64 + mt * 16 + h * 8 + mrow;
            int gr   = rowA0 + rloc;
            int labr = sLabR[rloc];
            float rd = 0.f, rm = 0.f;
            #pragma unroll
            for (int n8 = 0; n8 < 8; n8++) {
                #pragma unroll
                for (int j = 0; j < 2; j++) {
                    int cloc = wn * 64 + n8 * 8 + ncol + j;
                    int gc   = rowB0 + cloc;
                    float s  = acc[mt][n8][h * 2 + j];
                    if (gr < gc) {
                        float e = exp_poly(s);
                        float m = (labr == sLabC[cloc]) ? s : 0.f;
                        rd += e; rm += m;
                        cd[n8][j] += e; cm[n8][j] += m;
                    }
                }
            }
            #pragma unroll
            for (int o = 1; o <= 2; o <<= 1) {
                rd += __shfl_xor_sync(0xffffffffu, rd, o);
                rm += __shfl_xor_sync(0xffffffffu, rm, o);
            }
            if ((lane & 3) == 0) {
                atomicAdd(&g_den[gr], rd);
                atomicAdd(&g_nom[gr], rm);
            }
        }
    }
    #pragma unroll
    for (int n8 = 0; n8 < 8; n8++)
        #pragma unroll
        for (int j = 0; j < 2; j++) {
            #pragma unroll
            for (int o = 4; o <= 16; o <<= 1) {
                cd[n8][j] += __shfl_xor_sync(0xffffffffu, cd[n8][j], o);
                cm[n8][j] += __shfl_xor_sync(0xffffffffu, cm[n8][j], o);
            }
            if (lane < 4) {
                int gc = rowB0 + wn * 64 + n8 * 8 + (lane & 3) * 2 + j;
                atomicAdd(&g_den[gc], cd[n8][j]);
                atomicAdd(&g_nom[gc], cm[n8][j]);
            }
        }
}

// ---------------------------------------------------------------------------
__global__ void k_final(float* __restrict__ out) {
    __shared__ float part[4];
    int tid = threadIdx.x;  // 128
    float s = 0.f;
    #pragma unroll
    for (int i = 0; i < 32; i++) {
        int n = tid + i * 128;
        s += g_nom[n] / g_den[n];
    }
    #pragma unroll
    for (int o = 16; o; o >>= 1) s += __shfl_xor_sync(0xffffffffu, s, o);
    if ((tid & 31) == 0) part[tid >> 5] = s;
    __syncthreads();
    if (tid == 0) out[0] = (part[0] + part[1] + part[2] + part[3]) / 4096.0f;
}

// ---------------------------------------------------------------------------
extern "C" void kernel_launch(void* const* d_in, const int* in_sizes, int n_in,
                              void* d_out, int out_size) {
    const float* zi   = (const float*)d_in[0];
    const float* zj   = (const float*)d_in[1];
    // d_in[2] = z_n is dead code in the reference
    const float* dist = (const float*)d_in[3];
    float* out = (float*)d_out;

    cudaFuncSetAttribute(k_sim, cudaFuncAttributeMaxDynamicSharedMemorySize, SMEM_DYN);

    k_prep<<<1024, 256>>>(zi, zj, dist);
    k_sim<<<NTILES, 256, SMEM_DYN>>>();
    k_final<<<1, 128>>>(out);
}

// round 7
// speedup vs baseline: 2.5080x; 1.2834x over previous
#include <cuda_runtime.h>
#include <cuda_fp16.h>
#include <cstdint>

// NT-Xent loss. N=4096 (concat z_i,z_j), D=256, C=100.
// sim = x.x' computed as  xf*xf' (fp16 HMMA, K=256)
//                       + [a*e' + e*a'] / (127*2^19)  (int8 IMMA, K=512)
// where xf=fp16(x), e=x-xf, a=round(127*xf), e8=round(2^19*e).
// Identity: xf*xf' + xf*e' + e*xf' = x*x' - e*e'  (e*e' ~ 1e-9, negligible).
// Packed row layout g_pk[4096][1024B] = [a(256) | e8(256) | xf(512B)]:
//   chunk c (64B/row): A offset = 64c for all c in 0..15;
//   B offset = 64c+256 (c<4), 64c-256 (4<=c<8), 64c (c>=8).
// Tiles 256x128, elements counted iff gr<gc, scattered to both sides.
// Mainloop: 3-stage cp.async, 16 chunks: 8 IMMA chunks -> exact s32->f32 fold
// -> 8 HMMA chunks accumulate in place (register reuse, no spill).

#define BATCH 2048
#define N_TOT 4096
#define TM    256
#define TN    128
#define NTILES 272                        // sum_{R=0..15} (32-2R)
#define NCH   16                          // chunks of 64B/row
#define SROWB 80                          // smem row stride (5*16B, conflict-free)
#define A_STG (TM * SROWB)                // 20480
#define B_STG (TN * SROWB)                // 10240
#define B_OFF (3 * A_STG)
#define SMEM_DYN (3 * A_STG + 3 * B_STG)  // 92160
#define KCORR (1.0f / 66584576.0f)        // 1/(127*2^19)

__device__ __align__(16) unsigned char g_pk[(size_t)N_TOT * 1024];  // 4MB
__device__ int   g_lab[N_TOT];
__device__ float g_den[N_TOT];
__device__ float g_nom[N_TOT];

// ---------------------------------------------------------------------------
__device__ __forceinline__ uint32_t smem_u32(const void* p) {
    uint32_t a;
    asm("{ .reg .u64 t; cvta.to.shared.u64 t, %1; cvt.u32.u64 %0, t; }" : "=r"(a) : "l"(p));
    return a;
}
#define LDSM_X4(r0, r1, r2, r3, addr) \
    asm volatile("ldmatrix.sync.aligned.m8n8.x4.shared.b16 {%0,%1,%2,%3}, [%4];" \
                 : "=r"(r0), "=r"(r1), "=r"(r2), "=r"(r3) : "r"(addr))
__device__ __forceinline__ void cp_async16(uint32_t dst, const void* src) {
    asm volatile("cp.async.cg.shared.global [%0], [%1], 16;" :: "r"(dst), "l"(src));
}
#define CP_COMMIT() asm volatile("cp.async.commit_group;" ::: "memory")
#define CP_WAIT1()  asm volatile("cp.async.wait_group 1;" ::: "memory")

__device__ __forceinline__ void hmma_f16(float* d, const uint32_t* a,
                                         uint32_t b0, uint32_t b1) {
    asm volatile("mma.sync.aligned.m16n8k16.row.col.f32.f16.f16.f32 "
                 "{%0,%1,%2,%3}, {%4,%5,%6,%7}, {%8,%9}, {%0,%1,%2,%3};"
                 : "+f"(d[0]), "+f"(d[1]), "+f"(d[2]), "+f"(d[3])
                 : "r"(a[0]), "r"(a[1]), "r"(a[2]), "r"(a[3]), "r"(b0), "r"(b1));
}
__device__ __forceinline__ void imma_s8(int* d, const uint32_t* a,
                                        uint32_t b0, uint32_t b1) {
    asm volatile("mma.sync.aligned.m16n8k32.row.col.s32.s8.s8.s32 "
                 "{%0,%1,%2,%3}, {%4,%5,%6,%7}, {%8,%9}, {%0,%1,%2,%3};"
                 : "+r"(d[0]), "+r"(d[1]), "+r"(d[2]), "+r"(d[3])
                 : "r"(a[0]), "r"(a[1]), "r"(a[2]), "r"(a[3]), "r"(b0), "r"(b1));
}

// exp(x) on [-1,1], degree-9 Taylor (Horner). |abs err| < 3e-7, fma pipe only.
__device__ __forceinline__ float exp_poly(float x) {
    float p = 2.7557319e-6f;
    p = fmaf(p, x, 2.4801587e-5f);
    p = fmaf(p, x, 1.9841270e-4f);
    p = fmaf(p, x, 1.3888889e-3f);
    p = fmaf(p, x, 8.3333333e-3f);
    p = fmaf(p, x, 4.1666667e-2f);
    p = fmaf(p, x, 1.6666667e-1f);
    p = fmaf(p, x, 0.5f);
    p = fmaf(p, x, 1.0f);
    p = fmaf(p, x, 1.0f);
    return p;
}

__device__ __forceinline__ signed char q127(float v) {
    int q = __float2int_rn(v);
    q = max(-127, min(127, q));
    return (signed char)q;
}

// ---------------------------------------------------------------------------
// Prep: 1024 blocks x 256 threads; 4 rows/block, float4/thread.
__global__ void k_prep(const float* __restrict__ zi,
                       const float* __restrict__ zj,
                       const float* __restrict__ dist) {
    int tid  = threadIdx.x;
    int g    = tid >> 6;
    int t    = tid & 63;
    int lane = tid & 31, wid = tid >> 5;
    int row  = blockIdx.x * 4 + g;
    int srow = (row < BATCH) ? row : row - BATCH;
    const float* src = ((row < BATCH) ? zi : zj) + (size_t)srow * 256;

    float4 v = ((const float4*)src)[t];
    float ss = v.x * v.x + v.y * v.y + v.z * v.z + v.w * v.w;
    #pragma unroll
    for (int o = 16; o; o >>= 1) ss += __shfl_xor_sync(0xffffffffu, ss, o);

    __shared__ float wsum[8];
    __shared__ int   slab[4];
    if (lane == 0) wsum[wid] = ss;
    if (t < 50) {
        if (dist[(size_t)srow * 100 + t] > 0.5f)      slab[g] = t;
        if (dist[(size_t)srow * 100 + t + 50] > 0.5f) slab[g] = t + 50;
    }
    __syncthreads();

    float rn = 1.0f / sqrtf(wsum[2 * g] + wsum[2 * g + 1]);
    float x[4] = {v.x * rn, v.y * rn, v.z * rn, v.w * rn};

    unsigned char* pr = g_pk + (size_t)row * 1024;
    signed char a8[4], e8[4];
    __half xh[4];
    #pragma unroll
    for (int i = 0; i < 4; i++) {
        xh[i] = __float2half_rn(x[i]);
        float xf = __half2float(xh[i]);
        float e  = x[i] - xf;
        a8[i] = q127(xf * 127.0f);
        e8[i] = q127(e * 524288.0f);     // 2^19
    }
    *(char4*)(pr + t * 4)        = make_char4(a8[0], a8[1], a8[2], a8[3]);
    *(char4*)(pr + 256 + t * 4)  = make_char4(e8[0], e8[1], e8[2], e8[3]);
    __half2 p01 = __halves2half2(xh[0], xh[1]);
    __half2 p23 = __halves2half2(xh[2], xh[3]);
    uint2 hv = make_uint2(*(uint32_t*)&p01, *(uint32_t*)&p23);
    *(uint2*)(pr + 512 + t * 8) = hv;

    if (t == 0) {
        g_den[row] = 0.f;
        g_nom[row] = 0.f;
        g_lab[row] = slab[g];
    }
}

// ---------------------------------------------------------------------------
// k_sim: one 256x128 tile per CTA. 8 warps (4 over M x 2 over N), 64x64/warp.
__global__ void __launch_bounds__(256, 1) k_sim() {
    extern __shared__ char sm[];
    __shared__ int sLabR[TM], sLabC[TN];

    int tid  = threadIdx.x;
    int lane = tid & 31;
    int wid  = tid >> 5;
    int wm   = wid & 3;
    int wn   = wid >> 2;

    // decode linear tile id -> (R, C) with C >= 2R
    int t = blockIdx.x;
    int R = 0;
    while (t >= (32 - 2 * R)) { t -= (32 - 2 * R); R++; }
    int C = 2 * R + t;
    int rowA0 = R * TM;
    int rowB0 = C * TN;

    if (tid < TM) sLabR[tid] = g_lab[rowA0 + tid];
    if (tid < TN) sLabC[tid] = g_lab[rowB0 + tid];

    uint32_t smB = smem_u32(sm);

    // chunk c source byte offsets inside the 1KB packed row
    auto srcOffA = [](int c) { return c * 64; };
    auto srcOffB = [](int c) {
        return (c < 4) ? c * 64 + 256 : ((c < 8) ? c * 64 - 256 : c * 64);
    };

    auto issue = [&](int c, int st) {
        int oA = srcOffA(c), oB = srcOffB(c);
        #pragma unroll
        for (int u = 0; u < 4; u++) {                 // A: 1024 x 16B
            int idx = tid + u * 256, r = idx >> 2, ks = idx & 3;
            cp_async16(smB + st * A_STG + r * SROWB + ks * 16,
                       g_pk + (size_t)(rowA0 + r) * 1024 + oA + ks * 16);
        }
        #pragma unroll
        for (int u = 0; u < 2; u++) {                 // B: 512 x 16B
            int idx = tid + u * 256, r = idx >> 2, ks = idx & 3;
            cp_async16(smB + B_OFF + st * B_STG + r * SROWB + ks * 16,
                       g_pk + (size_t)(rowB0 + r) * 1024 + oB + ks * 16);
        }
        CP_COMMIT();
    };

    int acci[4][8][4];
    #pragma unroll
    for (int i = 0; i < 4; i++)
        #pragma unroll
        for (int j = 0; j < 8; j++)
            #pragma unroll
            for (int k = 0; k < 4; k++) acci[i][j][k] = 0;

    issue(0, 0);
    issue(1, 1);

    uint32_t aLane = (uint32_t)((wm * 64 + (lane & 15)) * SROWB + (lane >> 4) * 16);
    uint32_t bLane = (uint32_t)(B_OFF + (wn * 64 + (lane & 15)) * SROWB + (lane >> 4) * 16);

    // ---- phase 1: int8 correction, chunks 0..7 ----
    #pragma unroll 1
    for (int c = 0; c < 8; c++) {
        int st = c % 3;
        CP_WAIT1();
        __syncthreads();
        issue(c + 2, (c + 2) % 3);

        uint32_t aBase = smB + st * A_STG + aLane;
        uint32_t bBase = smB + st * B_STG + bLane;
        #pragma unroll
        for (int ks = 0; ks < 2; ks++) {              // 2 x k32 per 64B chunk
            uint32_t A[4][4];
            #pragma unroll
            for (int mt = 0; mt < 4; mt++)
                LDSM_X4(A[mt][0], A[mt][1], A[mt][2], A[mt][3],
                        aBase + mt * 16 * SROWB + ks * 32);
            #pragma unroll
            for (int ntp = 0; ntp < 4; ntp++) {
                uint32_t b[4];
                LDSM_X4(b[0], b[1], b[2], b[3], bBase + ntp * 16 * SROWB + ks * 32);
                #pragma unroll
                for (int mt = 0; mt < 4; mt++) {
                    imma_s8(acci[mt][ntp * 2],     A[mt], b[0], b[2]);
                    imma_s8(acci[mt][ntp * 2 + 1], A[mt], b[1], b[3]);
                }
            }
        }
    }

    // ---- fold: exact s32 -> fp32 (|S| <= 8.4e6 < 2^23), registers reused ----
    float accf[4][8][4];
    #pragma unroll
    for (int i = 0; i < 4; i++)
        #pragma unroll
        for (int j = 0; j < 8; j++)
            #pragma unroll
            for (int k = 0; k < 4; k++) accf[i][j][k] = (float)acci[i][j][k] * KCORR;

    // ---- phase 2: fp16 main product, chunks 8..15 ----
    #pragma unroll 1
    for (int c = 8; c < NCH; c++) {
        int st = c % 3;
        CP_WAIT1();
        __syncthreads();
        if (c + 2 < NCH) issue(c + 2, (c + 2) % 3);
        else CP_COMMIT();

        uint32_t aBase = smB + st * A_STG + aLane;
        uint32_t bBase = smB + st * B_STG + bLane;
        #pragma unroll
        for (int ks = 0; ks < 2; ks++) {              // 2 x k16 per 64B chunk
            uint32_t A[4][4];
            #pragma unroll
            for (int mt = 0; mt < 4; mt++)
                LDSM_X4(A[mt][0], A[mt][1], A[mt][2], A[mt][3],
                        aBase + mt * 16 * SROWB + ks * 32);
            #pragma unroll
            for (int ntp = 0; ntp < 4; ntp++) {
                uint32_t b[4];
                LDSM_X4(b[0], b[1], b[2], b[3], bBase + ntp * 16 * SROWB + ks * 32);
                #pragma unroll
                for (int mt = 0; mt < 4; mt++) {
                    hmma_f16(accf[mt][ntp * 2],     A[mt], b[0], b[2]);
                    hmma_f16(accf[mt][ntp * 2 + 1], A[mt], b[1], b[3]);
                }
            }
        }
    }

    // ---------------- epilogue: count (gr,gc) iff gr<gc, scatter both sides --
    int mrow = lane >> 2;
    int ncol = (lane & 3) * 2;

    float cd[8][2], cm[8][2];
    #pragma unroll
    for (int n8 = 0; n8 < 8; n8++) { cd[n8][0] = cd[n8][1] = 0.f; cm[n8][0] = cm[n8][1] = 0.f; }

    #pragma unroll
    for (int mt = 0; mt < 4; mt++) {
        #pragma unroll
        for (int h = 0; h < 2; h++) {
            int rloc = wm * 64 + mt * 16 + h * 8 + mrow;
            int gr   = rowA0 + rloc;
            int labr = sLabR[rloc];
            float rd = 0.f, rm = 0.f;
            #pragma unroll
            for (int n8 = 0; n8 < 8; n8++) {
                #pragma unroll
                for (int j = 0; j < 2; j++) {
                    int cloc = wn * 64 + n8 * 8 + ncol + j;
                    int gc   = rowB0 + cloc;
                    float s  = accf[mt][n8][h * 2 + j];
                    if (gr < gc) {
                        float e = exp_poly(s);
                        float m = (labr == sLabC[cloc]) ? s : 0.f;
                        rd += e; rm += m;
                        cd[n8][j] += e; cm[n8][j] += m;
                    }
                }
            }
            #pragma unroll
            for (int o = 1; o <= 2; o <<= 1) {
                rd += __shfl_xor_sync(0xffffffffu, rd, o);
                rm += __shfl_xor_sync(0xffffffffu, rm, o);
            }
            if ((lane & 3) == 0) {
                atomicAdd(&g_den[gr], rd);
                atomicAdd(&g_nom[gr], rm);
            }
        }
    }
    #pragma unroll
    for (int n8 = 0; n8 < 8; n8++)
        #pragma unroll
        for (int j = 0; j < 2; j++) {
            #pragma unroll
            for (int o = 4; o <= 16; o <<= 1) {
                cd[n8][j] += __shfl_xor_sync(0xffffffffu, cd[n8][j], o);
                cm[n8][j] += __shfl_xor_sync(0xffffffffu, cm[n8][j], o);
            }
            if (lane < 4) {
                int gc = rowB0 + wn * 64 + n8 * 8 + (lane & 3) * 2 + j;
                atomicAdd(&g_den[gc], cd[n8][j]);
                atomicAdd(&g_nom[gc], cm[n8][j]);
            }
        }
}

// ---------------------------------------------------------------------------
__global__ void k_final(float* __restrict__ out) {
    __shared__ float part[4];
    int tid = threadIdx.x;  // 128
    float s = 0.f;
    #pragma unroll
    for (int i = 0; i < 32; i++) {
        int n = tid + i * 128;
        s += g_nom[n] / g_den[n];
    }
    #pragma unroll
    for (int o = 16; o; o >>= 1) s += __shfl_xor_sync(0xffffffffu, s, o);
    if ((tid & 31) == 0) part[tid >> 5] = s;
    __syncthreads();
    if (tid == 0) out[0] = (part[0] + part[1] + part[2] + part[3]) / 4096.0f;
}

// ---------------------------------------------------------------------------
extern "C" void kernel_launch(void* const* d_in, const int* in_sizes, int n_in,
                              void* d_out, int out_size) {
    const float* zi   = (const float*)d_in[0];
    const float* zj   = (const float*)d_in[1];
    // d_in[2] = z_n is dead code in the reference
    const float* dist = (const float*)d_in[3];
    float* out = (float*)d_out;

    cudaFuncSetAttribute(k_sim, cudaFuncAttributeMaxDynamicSharedMemorySize, SMEM_DYN);

    k_prep<<<1024, 256>>>(zi, zj, dist);
    k_sim<<<NTILES, 256, SMEM_DYN>>>();
    k_final<<<1, 128>>>(out);
}

// round 8
// speedup vs baseline: 2.8657x; 1.1426x over previous
#include <cuda_runtime.h>
#include <cuda_fp16.h>
#include <cstdint>

// NT-Xent loss. N=4096 (concat z_i,z_j), D=256, C=100.
// sim = xf*xf' (fp16 HMMA, K=256) + [a*e' + e*a']/(127*2^19) (int8 IMMA, K=512)
// xf=fp16(x), e=x-xf, a=round(127*xf), e8=round(2^19*e).
// Packed row g_pk[4096][1024B] = [a(256) | e8(256) | xf(512B)].
// 8 K-chunks of 128B/row: chunks 0-3 IMMA (A=[a|e], B=[e|a]), 4-7 HMMA (xf).
// Tiles 256x128 (272 of them, C>=2R); element (gr,gc) counted iff gr<gc and
// scattered to both row gr and col gc -> each unordered pair exactly once.
// k_sim: 512 threads (8 M-warps x 2 N-warps, 32x64/warp) -> 4 warps/SMSP.
// 3-stage cp.async pipeline, in-place s32->f32 fold keeps regs <= 128.

#define BATCH 2048
#define N_TOT 4096
#define TM    256
#define TN    128
#define NTILES 272                        // sum_{R=0..15} (32-2R)
#define NCH   8                           // chunks of 128B/row
#define SROWB 144                         // smem row stride (9*16B, conflict-free)
#define A_STG (TM * SROWB)                // 36864
#define B_STG (TN * SROWB)                // 18432
#define B_OFF (3 * A_STG)                 // 110592
#define SMEM_DYN (3 * A_STG + 3 * B_STG)  // 165888
#define KCORR (1.0f / 66584576.0f)        // 1/(127*2^19)

__device__ __align__(16) unsigned char g_pk[(size_t)N_TOT * 1024];  // 4MB
__device__ int   g_lab[N_TOT];
__device__ float g_den[N_TOT];
__device__ float g_nom[N_TOT];

// ---------------------------------------------------------------------------
__device__ __forceinline__ uint32_t smem_u32(const void* p) {
    uint32_t a;
    asm("{ .reg .u64 t; cvta.to.shared.u64 t, %1; cvt.u32.u64 %0, t; }" : "=r"(a) : "l"(p));
    return a;
}
#define LDSM_X4(r0, r1, r2, r3, addr) \
    asm volatile("ldmatrix.sync.aligned.m8n8.x4.shared.b16 {%0,%1,%2,%3}, [%4];" \
                 : "=r"(r0), "=r"(r1), "=r"(r2), "=r"(r3) : "r"(addr))
__device__ __forceinline__ void cp_async16(uint32_t dst, const void* src) {
    asm volatile("cp.async.cg.shared.global [%0], [%1], 16;" :: "r"(dst), "l"(src));
}
#define CP_COMMIT() asm volatile("cp.async.commit_group;" ::: "memory")
#define CP_WAIT1()  asm volatile("cp.async.wait_group 1;" ::: "memory")

__device__ __forceinline__ void hmma_f16(float* d, const uint32_t* a,
                                         uint32_t b0, uint32_t b1) {
    asm volatile("mma.sync.aligned.m16n8k16.row.col.f32.f16.f16.f32 "
                 "{%0,%1,%2,%3}, {%4,%5,%6,%7}, {%8,%9}, {%0,%1,%2,%3};"
                 : "+f"(d[0]), "+f"(d[1]), "+f"(d[2]), "+f"(d[3])
                 : "r"(a[0]), "r"(a[1]), "r"(a[2]), "r"(a[3]), "r"(b0), "r"(b1));
}
__device__ __forceinline__ void imma_s8(int* d, const uint32_t* a,
                                        uint32_t b0, uint32_t b1) {
    asm volatile("mma.sync.aligned.m16n8k32.row.col.s32.s8.s8.s32 "
                 "{%0,%1,%2,%3}, {%4,%5,%6,%7}, {%8,%9}, {%0,%1,%2,%3};"
                 : "+r"(d[0]), "+r"(d[1]), "+r"(d[2]), "+r"(d[3])
                 : "r"(a[0]), "r"(a[1]), "r"(a[2]), "r"(a[3]), "r"(b0), "r"(b1));
}

// exp(x) on [-1,1], degree-9 Taylor (Horner). |abs err| < 3e-7, fma pipe only.
__device__ __forceinline__ float exp_poly(float x) {
    float p = 2.7557319e-6f;
    p = fmaf(p, x, 2.4801587e-5f);
    p = fmaf(p, x, 1.9841270e-4f);
    p = fmaf(p, x, 1.3888889e-3f);
    p = fmaf(p, x, 8.3333333e-3f);
    p = fmaf(p, x, 4.1666667e-2f);
    p = fmaf(p, x, 1.6666667e-1f);
    p = fmaf(p, x, 0.5f);
    p = fmaf(p, x, 1.0f);
    p = fmaf(p, x, 1.0f);
    return p;
}

__device__ __forceinline__ signed char q127(float v) {
    int q = __float2int_rn(v);
    q = max(-127, min(127, q));
    return (signed char)q;
}

// ---------------------------------------------------------------------------
// Prep: 1024 blocks x 256 threads; 4 rows/block, float4/thread.
__global__ void k_prep(const float* __restrict__ zi,
                       const float* __restrict__ zj,
                       const float* __restrict__ dist) {
    int tid  = threadIdx.x;
    int g    = tid >> 6;
    int t    = tid & 63;
    int lane = tid & 31, wid = tid >> 5;
    int row  = blockIdx.x * 4 + g;
    int srow = (row < BATCH) ? row : row - BATCH;
    const float* src = ((row < BATCH) ? zi : zj) + (size_t)srow * 256;

    float4 v = ((const float4*)src)[t];
    float ss = v.x * v.x + v.y * v.y + v.z * v.z + v.w * v.w;
    #pragma unroll
    for (int o = 16; o; o >>= 1) ss += __shfl_xor_sync(0xffffffffu, ss, o);

    __shared__ float wsum[8];
    __shared__ int   slab[4];
    if (lane == 0) wsum[wid] = ss;
    if (t < 50) {
        if (dist[(size_t)srow * 100 + t] > 0.5f)      slab[g] = t;
        if (dist[(size_t)srow * 100 + t + 50] > 0.5f) slab[g] = t + 50;
    }
    __syncthreads();

    float rn = 1.0f / sqrtf(wsum[2 * g] + wsum[2 * g + 1]);
    float x[4] = {v.x * rn, v.y * rn, v.z * rn, v.w * rn};

    unsigned char* pr = g_pk + (size_t)row * 1024;
    signed char a8[4], e8[4];
    __half xh[4];
    #pragma unroll
    for (int i = 0; i < 4; i++) {
        xh[i] = __float2half_rn(x[i]);
        float xf = __half2float(xh[i]);
        float e  = x[i] - xf;
        a8[i] = q127(xf * 127.0f);
        e8[i] = q127(e * 524288.0f);     // 2^19
    }
    *(char4*)(pr + t * 4)        = make_char4(a8[0], a8[1], a8[2], a8[3]);
    *(char4*)(pr + 256 + t * 4)  = make_char4(e8[0], e8[1], e8[2], e8[3]);
    __half2 p01 = __halves2half2(xh[0], xh[1]);
    __half2 p23 = __halves2half2(xh[2], xh[3]);
    uint2 hv = make_uint2(*(uint32_t*)&p01, *(uint32_t*)&p23);
    *(uint2*)(pr + 512 + t * 8) = hv;

    if (t == 0) {
        g_den[row] = 0.f;
        g_nom[row] = 0.f;
        g_lab[row] = slab[g];
    }
}

// ---------------------------------------------------------------------------
// k_sim: one 256x128 tile per CTA. 16 warps (8 over M x 2 over N), 32x64/warp.
__global__ void __launch_bounds__(512, 1) k_sim() {
    extern __shared__ char sm[];
    __shared__ int sLabR[TM], sLabC[TN];

    int tid  = threadIdx.x;
    int lane = tid & 31;
    int wid  = tid >> 5;
    int wm   = wid & 7;           // 8 warps over M (32 rows each)
    int wn   = wid >> 3;          // 2 warps over N (64 cols each)

    // decode linear tile id -> (R, C) with C >= 2R
    int t = blockIdx.x;
    int R = 0;
    while (t >= (32 - 2 * R)) { t -= (32 - 2 * R); R++; }
    int C = 2 * R + t;
    int rowA0 = R * TM;
    int rowB0 = C * TN;

    if (tid < TM) sLabR[tid] = g_lab[rowA0 + tid];
    if (tid < TN) sLabC[tid] = g_lab[rowB0 + tid];

    uint32_t smB = smem_u32(sm);

    // chunk c (128B/row) source offsets in the 1KB packed row
    auto srcOffA = [](int c) { return c * 128; };
    auto srcOffB = [](int c) {
        return (c < 2) ? c * 128 + 256 : ((c < 4) ? c * 128 - 256 : c * 128);
    };

    auto issue = [&](int c, int st) {
        int oA = srcOffA(c), oB = srcOffB(c);
        #pragma unroll
        for (int u = 0; u < 4; u++) {                 // A: 2048 x 16B
            int idx = tid + u * 512, r = idx >> 3, ks = idx & 7;
            cp_async16(smB + st * A_STG + r * SROWB + ks * 16,
                       g_pk + (size_t)(rowA0 + r) * 1024 + oA + ks * 16);
        }
        #pragma unroll
        for (int u = 0; u < 2; u++) {                 // B: 1024 x 16B
            int idx = tid + u * 512, r = idx >> 3, ks = idx & 7;
            cp_async16(smB + B_OFF + st * B_STG + r * SROWB + ks * 16,
                       g_pk + (size_t)(rowB0 + r) * 1024 + oB + ks * 16);
        }
        CP_COMMIT();
    };

    int acc[2][8][4];             // s32 in phase 1; refolded to f32 in place
    #pragma unroll
    for (int i = 0; i < 2; i++)
        #pragma unroll
        for (int j = 0; j < 8; j++)
            #pragma unroll
            for (int k = 0; k < 4; k++) acc[i][j][k] = 0;

    issue(0, 0);
    issue(1, 1);

    uint32_t aLane = (uint32_t)((wm * 32 + (lane & 15)) * SROWB + (lane >> 4) * 16);
    uint32_t bLane = (uint32_t)(B_OFF + (wn * 64 + (lane & 15)) * SROWB + (lane >> 4) * 16);

    // ---- phase 1: int8 correction, chunks 0..3 (4 x k32 per chunk) ----
    #pragma unroll 1
    for (int c = 0; c < 4; c++) {
        int st = c % 3;
        CP_WAIT1();
        __syncthreads();
        issue(c + 2, (c + 2) % 3);

        uint32_t aBase = smB + st * A_STG + aLane;
        uint32_t bBase = smB + st * B_STG + bLane;
        #pragma unroll
        for (int ks = 0; ks < 4; ks++) {
            uint32_t A[2][4];
            #pragma unroll
            for (int mt = 0; mt < 2; mt++)
                LDSM_X4(A[mt][0], A[mt][1], A[mt][2], A[mt][3],
                        aBase + mt * 16 * SROWB + ks * 32);
            #pragma unroll
            for (int ntp = 0; ntp < 4; ntp++) {
                uint32_t b[4];
                LDSM_X4(b[0], b[1], b[2], b[3], bBase + ntp * 16 * SROWB + ks * 32);
                #pragma unroll
                for (int mt = 0; mt < 2; mt++) {
                    imma_s8(acc[mt][ntp * 2],     A[mt], b[0], b[2]);
                    imma_s8(acc[mt][ntp * 2 + 1], A[mt], b[1], b[3]);
                }
            }
        }
    }

    // ---- fold in place: exact s32 -> f32 (|S| <= 8.4e6 < 2^23) ----
    float (*accf)[8][4] = (float(*)[8][4])acc;
    #pragma unroll
    for (int i = 0; i < 2; i++)
        #pragma unroll
        for (int j = 0; j < 8; j++)
            #pragma unroll
            for (int k = 0; k < 4; k++) {
                float f = (float)acc[i][j][k] * KCORR;
                accf[i][j][k] = f;
            }

    // ---- phase 2: fp16 main product, chunks 4..7 (4 x k16 per chunk) ----
    #pragma unroll 1
    for (int c = 4; c < NCH; c++) {
        int st = c % 3;
        CP_WAIT1();
        __syncthreads();
        if (c + 2 < NCH) issue(c + 2, (c + 2) % 3);
        else CP_COMMIT();

        uint32_t aBase = smB + st * A_STG + aLane;
        uint32_t bBase = smB + st * B_STG + bLane;
        #pragma unroll
        for (int ks = 0; ks < 4; ks++) {
            uint32_t A[2][4];
            #pragma unroll
            for (int mt = 0; mt < 2; mt++)
                LDSM_X4(A[mt][0], A[mt][1], A[mt][2], A[mt][3],
                        aBase + mt * 16 * SROWB + ks * 32);
            #pragma unroll
            for (int ntp = 0; ntp < 4; ntp++) {
                uint32_t b[4];
                LDSM_X4(b[0], b[1], b[2], b[3], bBase + ntp * 16 * SROWB + ks * 32);
                #pragma unroll
                for (int mt = 0; mt < 2; mt++) {
                    hmma_f16(accf[mt][ntp * 2],     A[mt], b[0], b[2]);
                    hmma_f16(accf[mt][ntp * 2 + 1], A[mt], b[1], b[3]);
                }
            }
        }
    }

    // ---------------- epilogue: count (gr,gc) iff gr<gc, scatter both sides --
    int mrow = lane >> 2;
    int ncol = (lane & 3) * 2;

    float cd[8][2], cm[8][2];
    #pragma unroll
    for (int n8 = 0; n8 < 8; n8++) { cd[n8][0] = cd[n8][1] = 0.f; cm[n8][0] = cm[n8][1] = 0.f; }

    #pragma unroll
    for (int mt = 0; mt < 2; mt++) {
        #pragma unroll
        for (int h = 0; h < 2; h++) {
            int rloc = wm * 32 + mt * 16 + h * 8 + mrow;
            int gr   = rowA0 + rloc;
            int labr = sLabR[rloc];
            float rd = 0.f, rm = 0.f;
            #pragma unroll
            for (int n8 = 0; n8 < 8; n8++) {
                #pragma unroll
                for (int j = 0; j < 2; j++) {
                    int cloc = wn * 64 + n8 * 8 + ncol + j;
                    int gc   = rowB0 + cloc;
                    float s  = accf[mt][n8][h * 2 + j];
                    if (gr < gc) {
                        float e = exp_poly(s);
                        float m = (labr == sLabC[cloc]) ? s : 0.f;
                        rd += e; rm += m;
                        cd[n8][j] += e; cm[n8][j] += m;
                    }
                }
            }
            #pragma unroll
            for (int o = 1; o <= 2; o <<= 1) {
                rd += __shfl_xor_sync(0xffffffffu, rd, o);
                rm += __shfl_xor_sync(0xffffffffu, rm, o);
            }
            if ((lane & 3) == 0) {
                atomicAdd(&g_den[gr], rd);
                atomicAdd(&g_nom[gr], rm);
            }
        }
    }
    #pragma unroll
    for (int n8 = 0; n8 < 8; n8++)
        #pragma unroll
        for (int j = 0; j < 2; j++) {
            #pragma unroll
            for (int o = 4; o <= 16; o <<= 1) {
                cd[n8][j] += __shfl_xor_sync(0xffffffffu, cd[n8][j], o);
                cm[n8][j] += __shfl_xor_sync(0xffffffffu, cm[n8][j], o);
            }
            if (lane < 4) {
                int gc = rowB0 + wn * 64 + n8 * 8 + (lane & 3) * 2 + j;
                atomicAdd(&g_den[gc], cd[n8][j]);
                atomicAdd(&g_nom[gc], cm[n8][j]);
            }
        }
}

// ---------------------------------------------------------------------------
__global__ void k_final(float* __restrict__ out) {
    __shared__ float part[4];
    int tid = threadIdx.x;  // 128
    float s = 0.f;
    #pragma unroll
    for (int i = 0; i < 32; i++) {
        int n = tid + i * 128;
        s += g_nom[n] / g_den[n];
    }
    #pragma unroll
    for (int o = 16; o; o >>= 1) s += __shfl_xor_sync(0xffffffffu, s, o);
    if ((tid & 31) == 0) part[tid >> 5] = s;
    __syncthreads();
    if (tid == 0) out[0] = (part[0] + part[1] + part[2] + part[3]) / 4096.0f;
}

// ---------------------------------------------------------------------------
extern "C" void kernel_launch(void* const* d_in, const int* in_sizes, int n_in,
                              void* d_out, int out_size) {
    const float* zi   = (const float*)d_in[0];
    const float* zj   = (const float*)d_in[1];
    // d_in[2] = z_n is dead code in the reference
    const float* dist = (const float*)d_in[3];
    float* out = (float*)d_out;

    cudaFuncSetAttribute(k_sim, cudaFuncAttributeMaxDynamicSharedMemorySize, SMEM_DYN);

    k_prep<<<1024, 256>>>(zi, zj, dist);
    k_sim<<<NTILES, 512, SMEM_DYN>>>();
    k_final<<<1, 128>>>(out);
}